// round 7
// baseline (speedup 1.0000x reference)
#include <cuda_runtime.h>
#include <math.h>

#define NMAX 16384
#define GMAX 1024
#define PI_F 3.14159265358979323846f

__device__ float g_node_f[NMAX * 2];
__device__ float g_eAB[NMAX * 2];
__device__ float g_upd[NMAX * 2];
__device__ float g_seg[GMAX * 2];
__device__ float g_cnt[GMAX];
__device__ int   g_ctr;

__device__ __forceinline__ float leaky(float x) { return x > 0.f ? x : 0.2f * x; }

__device__ __forceinline__ float ldcg(const float* p) {
    float v; asm volatile("ld.global.cg.f32 %0, [%1];" : "=f"(v) : "l"(p)); return v;
}

// ---------------- K1: 4 rows per warp, weights register-resident ------------
__global__ void __launch_bounds__(128, 1)
k1_feat(const float* __restrict__ node_feat, int N,
        const float* __restrict__ edge_attr,
        const float* __restrict__ nW1, const float* __restrict__ nb1,
        const float* __restrict__ nW2, const float* __restrict__ nb2,
        const float* __restrict__ eW1, const float* __restrict__ eb1,
        const float* __restrict__ eW2, const float* __restrict__ eb2,
        const int* __restrict__ ge)
{
    int tid = threadIdx.x;
    int lane = tid & 31;
    int w = tid >> 5;
    int gtid = blockIdx.x * blockDim.x + tid;

    if (gtid < GMAX * 2) g_seg[gtid] = 0.f;
    else if (gtid < GMAX * 3) g_cnt[gtid - GMAX * 2] = 0.f;
    if (gtid == 0) g_ctr = 0;

    int j0 = 4 * lane;

    float wn[16][4];
#pragma unroll
    for (int k = 0; k < 16; k++) {
#pragma unroll
        for (int q = 0; q < 4; q++) wn[k][q] = __ldg(nW1 + k * 128 + j0 + q);
    }
    float bn[4], n2[4][2];
#pragma unroll
    for (int q = 0; q < 4; q++) {
        bn[q] = __ldg(nb1 + j0 + q);
        n2[q][0] = __ldg(nW2 + 2 * (j0 + q) + 0);
        n2[q][1] = __ldg(nW2 + 2 * (j0 + q) + 1);
    }
    float we[8][4];
#pragma unroll
    for (int k = 0; k < 8; k++) {
#pragma unroll
        for (int q = 0; q < 4; q++) we[k][q] = __ldg(eW1 + k * 128 + j0 + q);
    }
    float be[4], e2[4][2];
#pragma unroll
    for (int q = 0; q < 4; q++) {
        be[q] = __ldg(eb1 + j0 + q);
        e2[q][0] = __ldg(eW2 + 2 * (j0 + q) + 0);
        e2[q][1] = __ldg(eW2 + 2 * (j0 + q) + 1);
    }
    float nb2x = __ldg(nb2 + 0), nb2y = __ldg(nb2 + 1);
    float eb2x = __ldg(eb2 + 0), eb2y = __ldg(eb2 + 1);

    int warpId = blockIdx.x * (blockDim.x >> 5) + w;
    int base = warpId * 4;

#pragma unroll
    for (int rr = 0; rr < 4; rr++) {
        int row = base + rr;
        bool valid = row < N;
        int ic = min(row, N - 1);

        float x[16];
#pragma unroll
        for (int k = 0; k < 16; k++) x[k] = __ldg(node_feat + ic * 16 + k);

        float h[4] = {bn[0], bn[1], bn[2], bn[3]};
#pragma unroll
        for (int k = 0; k < 16; k++) {
#pragma unroll
            for (int q = 0; q < 4; q++) h[q] = fmaf(x[k], wn[k][q], h[q]);
        }
        float o0 = 0.f, o1 = 0.f;
#pragma unroll
        for (int q = 0; q < 4; q++) {
            float hq = leaky(h[q]);
            o0 = fmaf(hq, n2[q][0], o0);
            o1 = fmaf(hq, n2[q][1], o1);
        }

        int eidx = __ldg(ge + ic * 3);
        int ec = max(eidx, 0);
        float y[8];
#pragma unroll
        for (int k = 0; k < 8; k++) y[k] = __ldg(edge_attr + ec * 8 + k);

        float g[4] = {be[0], be[1], be[2], be[3]};
#pragma unroll
        for (int k = 0; k < 8; k++) {
#pragma unroll
            for (int q = 0; q < 4; q++) g[q] = fmaf(y[k], we[k][q], g[q]);
        }
        float p0 = 0.f, p1 = 0.f;
#pragma unroll
        for (int q = 0; q < 4; q++) {
            float gq = leaky(g[q]);
            p0 = fmaf(gq, e2[q][0], p0);
            p1 = fmaf(gq, e2[q][1], p1);
        }

#pragma unroll
        for (int off = 16; off >= 1; off >>= 1) {
            o0 += __shfl_xor_sync(0xffffffffu, o0, off);
            o1 += __shfl_xor_sync(0xffffffffu, o1, off);
            p0 += __shfl_xor_sync(0xffffffffu, p0, off);
            p1 += __shfl_xor_sync(0xffffffffu, p1, off);
        }

        if (lane == 0 && valid) {
            g_node_f[row * 2 + 0] = tanhf(o0 + nb2x) * PI_F;
            g_node_f[row * 2 + 1] = tanhf(o1 + nb2y) * PI_F;
            g_eAB[row * 2 + 0] = (eidx >= 0) ? tanhf(p0 + eb2x) * PI_F : 0.f;
            g_eAB[row * 2 + 1] = (eidx >= 0) ? tanhf(p1 + eb2y) * PI_F : 0.f;
        }
    }
}

// ---------------- K2: one thread per row, 16-amp chi in NAMED registers -----
// amp index bits: q0=1, q4=2, q7=4, q8=8.

#define CRX_P(lr,li,hr,hi,c,s) { float t0=lr,t1=li,t2=hr,t3=hi; \
  lr=c*t0+s*t3; li=c*t1-s*t2; hr=c*t2+s*t1; hi=c*t3-s*t0; }
#define CRY_P(lr,li,hr,hi,c,s) { float t0=lr,t1=li,t2=hr,t3=hi; \
  lr=c*t0-s*t2; li=c*t1-s*t3; hr=s*t0+c*t2; hi=s*t1+c*t3; }
#define RZP(re,im,c,s) { float t=re; re=c*t-s*(im); im=c*(im)+s*t; }
#define RZM(re,im,c,s) { float t=re; re=c*t+s*(im); im=c*(im)-s*t; }
#define UPAIR(lr,li,hr,hi) { float t0=lr,t1=li,t2=hr,t3=hi; \
  lr = U0*t0 - U1*t1 + U2*t2 - U3*t3; \
  li = U0*t1 + U1*t0 + U2*t3 + U3*t2; \
  hr = U4*t0 - U5*t1 + U6*t2 - U7*t3; \
  hi = U4*t1 + U5*t0 + U6*t3 + U7*t2; }
#define LOADUg(g) { U0=sU[g][0]; U1=sU[g][1]; U2=sU[g][2]; U3=sU[g][3]; \
                    U4=sU[g][4]; U5=sU[g][5]; U6=sU[g][6]; U7=sU[g][7]; }
#define NEGA(m) { r##m = -r##m; i##m = -i##m; }
#define OBS(a,b,A,B) { \
  float uar = d8*r##a + k8r*r##A - k8i*i##A; \
  float uai = d8*i##a + k8r*i##A + k8i*r##A; \
  float uAr = k8r*r##a + k8i*i##a - d8*r##A; \
  float uAi = k8r*i##a - k8i*r##a - d8*i##A; \
  float ubr = d8*r##b + k8r*r##B - k8i*i##B; \
  float ubi = d8*i##b + k8r*i##B + k8i*r##B; \
  float uBr = k8r*r##b + k8i*i##b - d8*r##B; \
  float uBi = k8r*i##b - k8i*r##b - d8*i##B; \
  S += d7*(r##a*uar + i##a*uai - (r##b*ubr + i##b*ubi)); \
  S += r##a*(k7r*ubr - k7i*ubi) + i##a*(k7r*ubi + k7i*ubr); \
  S += r##b*(k7r*uar + k7i*uai) + i##b*(k7r*uai - k7i*uar); \
  S += d7*(r##A*uAr + i##A*uAi - (r##B*uBr + i##B*uBi)); \
  S += r##A*(k7r*uBr - k7i*uBi) + i##A*(k7r*uBi + k7i*uBr); \
  S += r##B*(k7r*uAr + k7i*uAi) + i##B*(k7r*uAi - k7i*uAr); }

__global__ void __launch_bounds__(32, 1)
k2_pqc(int N, int mode, int G,
       const float* __restrict__ theta,
       const float* __restrict__ uW1, const float* __restrict__ ub1,
       const float* __restrict__ uW2, const float* __restrict__ ub2,
       const int* __restrict__ gn, const int* __restrict__ batch,
       const float* __restrict__ hW1, const float* __restrict__ hb1,
       const float* __restrict__ hW2, const float* __restrict__ hb2,
       float* __restrict__ out)
{
    __shared__ float sU[7][8];
    __shared__ float sM[6];
    __shared__ float4 sP1[128];
    __shared__ float2 sP2[128];
    __shared__ float sb2v[2];
    __shared__ int s_last;
    int tid = threadIdx.x;

    if (tid < 9) {
        int g = tid;
        float sx, cx, sy, cy, sz, cz;
        sincosf(0.5f * theta[3 * g + 0], &sx, &cx);
        sincosf(0.5f * theta[3 * g + 1], &sy, &cy);
        sincosf(0.5f * theta[3 * g + 2], &sz, &cz);
        float M00r =  cy*cx, M00i =  sy*sx;
        float M01r = -sy*cx, M01i = -cy*sx;
        float M10r =  sy*cx, M10i = -cy*sx;
        float M11r =  cy*cx, M11i = -sy*sx;
        float u[8];
        u[0] = cz*M00r + sz*M00i;  u[1] = cz*M00i - sz*M00r;
        u[2] = cz*M01r + sz*M01i;  u[3] = cz*M01i - sz*M01r;
        u[4] = cz*M10r - sz*M10i;  u[5] = cz*M10i + sz*M10r;
        u[6] = cz*M11r - sz*M11i;  u[7] = cz*M11i + sz*M11r;
        if (g < 7) {
#pragma unroll
            for (int k = 0; k < 8; k++) sU[g][k] = u[k];
        } else {
            int off = (g == 7) ? 0 : 3;
            sM[off + 0] = u[0]*u[0] + u[1]*u[1] - (u[4]*u[4] + u[5]*u[5]);
            sM[off + 1] = u[0]*u[2] + u[1]*u[3] - (u[4]*u[6] + u[5]*u[7]);
            sM[off + 2] = u[0]*u[3] - u[1]*u[2] - (u[4]*u[7] - u[5]*u[6]);
        }
    }
    for (int j = tid; j < 128; j += 32) {
        sP1[j] = make_float4(__ldg(uW1 + j), __ldg(uW1 + 128 + j),
                             __ldg(uW1 + 256 + j), __ldg(ub1 + j));
        sP2[j] = make_float2(__ldg(uW2 + 2*j + 0), __ldg(uW2 + 2*j + 1));
    }
    if (tid < 2) sb2v[tid] = ub2[tid];
    __syncthreads();

    int row = blockIdx.x * 32 + tid;
    int i = min(row, N - 1);
    bool valid = row < N;

    int i0 = __ldg(gn + i * 4 + 0), i1 = __ldg(gn + i * 4 + 1);
    int i0c = max(i0, 0), i1c = max(i1, 0);
    float nf0u = g_node_f[i0c * 2 + 0];
    float nf1u = g_node_f[i0c * 2 + 1];
    float nA0 = (i0 >= 0) ? nf0u : 0.f;
    float nA1 = (i0 >= 0) ? nf1u : 0.f;
    float nB0 = (i1 >= 0) ? g_node_f[i1c * 2 + 0] : 0.f;
    float nB1 = (i1 >= 0) ? g_node_f[i1c * 2 + 1] : 0.f;
    float eA = g_eAB[i * 2 + 0], eB = g_eAB[i * 2 + 1];

    float cA, sA, cB, sB, c3a, s3a, c3b, s3b, c4a, s4a, c4b, s4b;
    __sincosf(0.5f * eA,  &sA,  &cA);
    __sincosf(0.5f * eB,  &sB,  &cB);
    __sincosf(0.5f * nA0, &s3a, &c3a);
    __sincosf(0.5f * nA1, &s3b, &c3b);
    __sincosf(0.5f * nB0, &s4a, &c4a);
    __sincosf(0.5f * nB1, &s4b, &c4b);

    // product init on (q0,q4); q7=q8=|0>
    float f0r0 = cA*cB,   f0i0 = -cA*sB,   f0r1 = sA*cB,   f0i1 = sA*sB;
    float f4r0 = c4a*c4b, f4i0 = -c4a*s4b, f4r1 = s4a*c4b, f4i1 = s4a*s4b;

    float r0 = f0r0*f4r0 - f0i0*f4i0, i0_ = f0r0*f4i0 + f0i0*f4r0;
    float r1 = f0r1*f4r0 - f0i1*f4i0, i1_ = f0r1*f4i0 + f0i1*f4r0;
    float r2 = f0r0*f4r1 - f0i0*f4i1, i2 = f0r0*f4i1 + f0i0*f4r1;
    float r3 = f0r1*f4r1 - f0i1*f4i1, i3 = f0r1*f4i1 + f0i1*f4r1;
    float r4=0.f,i4=0.f,r5=0.f,i5=0.f,r6=0.f,i6=0.f,r7=0.f,i7=0.f;
    float r8=0.f,i8=0.f,r9=0.f,i9=0.f,r10=0.f,i10=0.f,r11=0.f,i11=0.f;
    float r12=0.f,i12=0.f,r13=0.f,i13=0.f,r14=0.f,i14=0.f,r15=0.f,i15=0.f;
    // rename to match macro naming (i0,i1 clash with indices)
    float i0v = i0_, i1v = i1_;
#define i0 i0v
#define i1 i1v

    // CRX(nB0): c=q4(bit1), t=q7(bit2): pairs (2,6)(3,7)(10,14)(11,15)
    CRX_P(r2,i2,r6,i6,c4a,s4a)   CRX_P(r3,i3,r7,i7,c4a,s4a)
    CRX_P(r10,i10,r14,i14,c4a,s4a) CRX_P(r11,i11,r15,i15,c4a,s4a)
    // CRY(eA): c=q0(bit0), t=q7(bit2): pairs (1,5)(3,7)(9,13)(11,15)
    CRY_P(r1,i1,r5,i5,cA,sA)     CRY_P(r3,i3,r7,i7,cA,sA)
    CRY_P(r9,i9,r13,i13,cA,sA)   CRY_P(r11,i11,r15,i15,cA,sA)
    // CRZ(nB1): c=q4(bit1), t=q8(bit3): minus-phase {2,3,6,7}, plus {10,11,14,15}
    RZM(r2,i2,c4b,s4b)  RZM(r3,i3,c4b,s4b)  RZM(r6,i6,c4b,s4b)  RZM(r7,i7,c4b,s4b)
    RZP(r10,i10,c4b,s4b) RZP(r11,i11,c4b,s4b) RZP(r14,i14,c4b,s4b) RZP(r15,i15,c4b,s4b)
    // CRY(eB): c=q0(bit0), t=q8(bit3): pairs (1,9)(3,11)(5,13)(7,15)
    CRY_P(r1,i1,r9,i9,cB,sB)     CRY_P(r3,i3,r11,i11,cB,sB)
    CRY_P(r5,i5,r13,i13,cB,sB)   CRY_P(r7,i7,r15,i15,cB,sB)

    float U0,U1,U2,U3,U4,U5,U6,U7;

    // Block 0: U0 on q0(bit0), U1 on q4(bit1), U2 on q7(bit2)
    LOADUg(0)
    UPAIR(r0,i0,r1,i1)   UPAIR(r2,i2,r3,i3)   UPAIR(r4,i4,r5,i5)   UPAIR(r6,i6,r7,i7)
    UPAIR(r8,i8,r9,i9)   UPAIR(r10,i10,r11,i11) UPAIR(r12,i12,r13,i13) UPAIR(r14,i14,r15,i15)
    LOADUg(1)
    UPAIR(r0,i0,r2,i2)   UPAIR(r1,i1,r3,i3)   UPAIR(r4,i4,r6,i6)   UPAIR(r5,i5,r7,i7)
    UPAIR(r8,i8,r10,i10) UPAIR(r9,i9,r11,i11) UPAIR(r12,i12,r14,i14) UPAIR(r13,i13,r15,i15)
    LOADUg(2)
    UPAIR(r0,i0,r4,i4)   UPAIR(r1,i1,r5,i5)   UPAIR(r2,i2,r6,i6)   UPAIR(r3,i3,r7,i7)
    UPAIR(r8,i8,r12,i12) UPAIR(r9,i9,r13,i13) UPAIR(r10,i10,r14,i14) UPAIR(r11,i11,r15,i15)
    // CZ(0,4) CZ(4,7) CZ(7,0): negate m with popc(m&7)>=2 -> {3,5,6,7,11,13,14,15}
    NEGA(3) NEGA(5) NEGA(6) NEGA(7) NEGA(11) NEGA(13) NEGA(14) NEGA(15)

    // Block 1: U3 on q7(bit2), U4 on q4(bit1), U5 on q8(bit3)
    LOADUg(3)
    UPAIR(r0,i0,r4,i4)   UPAIR(r1,i1,r5,i5)   UPAIR(r2,i2,r6,i6)   UPAIR(r3,i3,r7,i7)
    UPAIR(r8,i8,r12,i12) UPAIR(r9,i9,r13,i13) UPAIR(r10,i10,r14,i14) UPAIR(r11,i11,r15,i15)
    LOADUg(4)
    UPAIR(r0,i0,r2,i2)   UPAIR(r1,i1,r3,i3)   UPAIR(r4,i4,r6,i6)   UPAIR(r5,i5,r7,i7)
    UPAIR(r8,i8,r10,i10) UPAIR(r9,i9,r11,i11) UPAIR(r12,i12,r14,i14) UPAIR(r13,i13,r15,i15)
    LOADUg(5)
    UPAIR(r0,i0,r8,i8)   UPAIR(r1,i1,r9,i9)   UPAIR(r2,i2,r10,i10) UPAIR(r3,i3,r11,i11)
    UPAIR(r4,i4,r12,i12) UPAIR(r5,i5,r13,i13) UPAIR(r6,i6,r14,i14) UPAIR(r7,i7,r15,i15)
    // CZ(7,4) CZ(4,8) CZ(8,7): negate m with popc(m&14)>=2 -> {6,7,10,11,12,13,14,15}
    NEGA(6) NEGA(7) NEGA(10) NEGA(11) NEGA(12) NEGA(13) NEGA(14) NEGA(15)

    // S = <chi| M7(q7) (x) M8(q8) |chi>
    float d7 = sM[0], k7r = sM[1], k7i = sM[2];
    float d8 = sM[3], k8r = sM[4], k8i = sM[5];
    float S = 0.f;
    OBS(0,4,8,12) OBS(1,5,9,13) OBS(2,6,10,14) OBS(3,7,11,15)

    // q3 scalar
    LOADUg(6)
    {
        float p0r = c3a*c3b, p0i = -c3a*s3b, p1r = s3a*c3b, p1i = s3a*s3b;
        float a0r = U0*p0r - U1*p0i + U2*p1r - U3*p1i;
        float a0i = U0*p0i + U1*p0r + U2*p1i + U3*p1r;
        float a1r = U4*p0r - U5*p0i + U6*p1r - U7*p1i;
        float a1i = U4*p0i + U5*p0r + U6*p1i + U7*p1r;
        S *= 2.f * (a0r*a1r + a0i*a1i);
    }
    float ex = S;
#undef i0
#undef i1

    // upd MLP: 3 -> 128 (leaky) -> 2, broadcast LDS
    float acc0 = sb2v[0], acc1 = sb2v[1];
#pragma unroll 4
    for (int j = 0; j < 128; j++) {
        float4 wv = sP1[j];
        float h = fmaf(nf0u, wv.x, fmaf(nf1u, wv.y, fmaf(ex, wv.z, wv.w)));
        h = leaky(h);
        float2 v = sP2[j];
        acc0 = fmaf(h, v.x, acc0);
        acc1 = fmaf(h, v.y, acc1);
    }

    if (valid) {
        if (mode == 1) {
            int gi = batch[i];
            atomicAdd(&g_seg[gi * 2 + 0], g_node_f[i * 2 + 0]);
            atomicAdd(&g_seg[gi * 2 + 1], g_node_f[i * 2 + 1]);
            atomicAdd(&g_cnt[gi], 1.f);
            int gt = batch[i0c];
            atomicAdd(&g_seg[gt * 2 + 0], acc0);
            atomicAdd(&g_seg[gt * 2 + 1], acc1);
        } else {
            g_upd[i * 2 + 0] = acc0;
            g_upd[i * 2 + 1] = acc1;
        }
    }

    if (mode == 1) {
        __threadfence();
        __syncthreads();
        if (tid == 0) s_last = (atomicAdd(&g_ctr, 1) == (int)gridDim.x - 1) ? 1 : 0;
        __syncthreads();
        if (s_last) {
            for (int g = tid; g < G; g += 32) {
                float c = ldcg(&g_cnt[g]);
                float inv = (c > 0.f) ? (1.f / c) : 0.f;
                float e0 = ldcg(&g_seg[g * 2 + 0]) * inv;
                float e1 = ldcg(&g_seg[g * 2 + 1]) * inv;
                float h0 = leaky(e0 * hW1[0] + e1 * hW1[2] + hb1[0]);
                float h1 = leaky(e0 * hW1[1] + e1 * hW1[3] + hb1[1]);
                out[g * 2 + 0] = h0 * hW2[0] + h1 * hW2[2] + hb2[0];
                out[g * 2 + 1] = h0 * hW2[1] + h1 * hW2[3] + hb2[1];
            }
        }
    }
}

// ---------------- multi-hop helpers (H > 1 only) ----------------------------
__global__ void k2_scatter(int N, const int* __restrict__ gn)
{
    int i = blockIdx.x * blockDim.x + threadIdx.x;
    if (i >= N) return;
    int t = max(gn[i * 4], 0);
    atomicAdd(&g_node_f[t * 2 + 0], g_upd[i * 2 + 0]);
    atomicAdd(&g_node_f[t * 2 + 1], g_upd[i * 2 + 1]);
}

__global__ void k_seg(int N, const int* __restrict__ batch)
{
    int i = blockIdx.x * blockDim.x + threadIdx.x;
    if (i >= N) return;
    int g = batch[i];
    atomicAdd(&g_seg[g * 2 + 0], g_node_f[i * 2 + 0]);
    atomicAdd(&g_seg[g * 2 + 1], g_node_f[i * 2 + 1]);
    atomicAdd(&g_cnt[g], 1.f);
}

__global__ void k3_head(int G,
                        const float* __restrict__ hW1, const float* __restrict__ hb1,
                        const float* __restrict__ hW2, const float* __restrict__ hb2,
                        float* __restrict__ out)
{
    int g = blockIdx.x * blockDim.x + threadIdx.x;
    if (g >= G) return;
    float c = g_cnt[g];
    float inv = (c > 0.f) ? (1.f / c) : 0.f;
    float e0 = g_seg[g * 2 + 0] * inv;
    float e1 = g_seg[g * 2 + 1] * inv;
    float h0 = leaky(e0 * hW1[0] + e1 * hW1[2] + hb1[0]);
    float h1 = leaky(e0 * hW1[1] + e1 * hW1[3] + hb1[1]);
    out[g * 2 + 0] = h0 * hW2[0] + h1 * hW2[2] + hb2[0];
    out[g * 2 + 1] = h0 * hW2[1] + h1 * hW2[3] + hb2[1];
}

extern "C" void kernel_launch(void* const* d_in, const int* in_sizes, int n_in,
                              void* d_out, int out_size)
{
    const float* node_feat = (const float*)d_in[0];
    const float* edge_attr = (const float*)d_in[1];
    const float* nW1 = (const float*)d_in[2];
    const float* nb1 = (const float*)d_in[3];
    const float* nW2 = (const float*)d_in[4];
    const float* nb2 = (const float*)d_in[5];
    const float* eW1 = (const float*)d_in[6];
    const float* eb1 = (const float*)d_in[7];
    const float* eW2 = (const float*)d_in[8];
    const float* eb2 = (const float*)d_in[9];
    const float* theta = (const float*)d_in[10];
    const float* uW1 = (const float*)d_in[11];
    const float* ub1 = (const float*)d_in[12];
    const float* uW2 = (const float*)d_in[13];
    const float* ub2 = (const float*)d_in[14];
    const float* hW1 = (const float*)d_in[15];
    const float* hb1 = (const float*)d_in[16];
    const float* hW2 = (const float*)d_in[17];
    const float* hb2 = (const float*)d_in[18];
    const int* gn = (const int*)d_in[19];
    const int* ge = (const int*)d_in[20];
    const int* batch = (const int*)d_in[21];

    int N = in_sizes[0] / 16;
    int H = in_sizes[10] / 27;
    int G = out_size / 2;

    int k1blocks = (N + 15) / 16;
    k1_feat<<<k1blocks, 128>>>(node_feat, N, edge_attr, nW1, nb1, nW2, nb2,
                               eW1, eb1, eW2, eb2, ge);

    int k2blocks = (N + 31) / 32;
    if (H == 1) {
        k2_pqc<<<k2blocks, 32>>>(N, 1, G, theta, uW1, ub1, uW2, ub2, gn, batch,
                                 hW1, hb1, hW2, hb2, (float*)d_out);
    } else {
        const int T = 128;
        int nbs = (N + T - 1) / T;
        for (int h = 0; h < H; h++) {
            k2_pqc<<<k2blocks, 32>>>(N, 0, G, theta + 27 * h,
                                     uW1 + 384 * h, ub1 + 128 * h,
                                     uW2 + 256 * h, ub2 + 2 * h, gn, batch,
                                     hW1, hb1, hW2, hb2, (float*)d_out);
            k2_scatter<<<nbs, T>>>(N, gn);
        }
        k_seg<<<nbs, T>>>(N, batch);
        k3_head<<<(G + 127) / 128, 128>>>(G, hW1, hb1, hW2, hb2, (float*)d_out);
    }
}

// round 8
// speedup vs baseline: 1.0616x; 1.0616x over previous
#include <cuda_runtime.h>
#include <math.h>

#define NMAX 16384
#define GMAX 1024
#define PI_F 3.14159265358979323846f

__device__ float g_node_f[NMAX * 2];
__device__ float g_eAB[NMAX * 2];
__device__ float g_upd[NMAX * 2];
__device__ float g_seg[GMAX * 2];
__device__ float g_cnt[GMAX];
__device__ int   g_ctr;

__device__ __forceinline__ float leaky(float x) { return x > 0.f ? x : 0.2f * x; }

__device__ __forceinline__ float ldcg(const float* p) {
    float v; asm volatile("ld.global.cg.f32 %0, [%1];" : "=f"(v) : "l"(p)); return v;
}

// ---------------- K1: 4 rows per warp, weights register-resident ------------
__global__ void __launch_bounds__(128, 1)
k1_feat(const float* __restrict__ node_feat, int N,
        const float* __restrict__ edge_attr,
        const float* __restrict__ nW1, const float* __restrict__ nb1,
        const float* __restrict__ nW2, const float* __restrict__ nb2,
        const float* __restrict__ eW1, const float* __restrict__ eb1,
        const float* __restrict__ eW2, const float* __restrict__ eb2,
        const int* __restrict__ ge)
{
    int tid = threadIdx.x;
    int lane = tid & 31;
    int w = tid >> 5;
    int gtid = blockIdx.x * blockDim.x + tid;

    if (gtid < GMAX * 2) g_seg[gtid] = 0.f;
    else if (gtid < GMAX * 3) g_cnt[gtid - GMAX * 2] = 0.f;
    if (gtid == 0) g_ctr = 0;

    int j0 = 4 * lane;

    float wn[16][4];
#pragma unroll
    for (int k = 0; k < 16; k++) {
#pragma unroll
        for (int q = 0; q < 4; q++) wn[k][q] = __ldg(nW1 + k * 128 + j0 + q);
    }
    float bn[4], n2[4][2];
#pragma unroll
    for (int q = 0; q < 4; q++) {
        bn[q] = __ldg(nb1 + j0 + q);
        n2[q][0] = __ldg(nW2 + 2 * (j0 + q) + 0);
        n2[q][1] = __ldg(nW2 + 2 * (j0 + q) + 1);
    }
    float we[8][4];
#pragma unroll
    for (int k = 0; k < 8; k++) {
#pragma unroll
        for (int q = 0; q < 4; q++) we[k][q] = __ldg(eW1 + k * 128 + j0 + q);
    }
    float be[4], e2[4][2];
#pragma unroll
    for (int q = 0; q < 4; q++) {
        be[q] = __ldg(eb1 + j0 + q);
        e2[q][0] = __ldg(eW2 + 2 * (j0 + q) + 0);
        e2[q][1] = __ldg(eW2 + 2 * (j0 + q) + 1);
    }
    float nb2x = __ldg(nb2 + 0), nb2y = __ldg(nb2 + 1);
    float eb2x = __ldg(eb2 + 0), eb2y = __ldg(eb2 + 1);

    int warpId = blockIdx.x * (blockDim.x >> 5) + w;
    int base = warpId * 4;

#pragma unroll
    for (int rr = 0; rr < 4; rr++) {
        int row = base + rr;
        bool valid = row < N;
        int ic = min(row, N - 1);

        float x[16];
#pragma unroll
        for (int k = 0; k < 16; k++) x[k] = __ldg(node_feat + ic * 16 + k);

        float h[4] = {bn[0], bn[1], bn[2], bn[3]};
#pragma unroll
        for (int k = 0; k < 16; k++) {
#pragma unroll
            for (int q = 0; q < 4; q++) h[q] = fmaf(x[k], wn[k][q], h[q]);
        }
        float o0 = 0.f, o1 = 0.f;
#pragma unroll
        for (int q = 0; q < 4; q++) {
            float hq = leaky(h[q]);
            o0 = fmaf(hq, n2[q][0], o0);
            o1 = fmaf(hq, n2[q][1], o1);
        }

        int eidx = __ldg(ge + ic * 3);
        int ec = max(eidx, 0);
        float y[8];
#pragma unroll
        for (int k = 0; k < 8; k++) y[k] = __ldg(edge_attr + ec * 8 + k);

        float g[4] = {be[0], be[1], be[2], be[3]};
#pragma unroll
        for (int k = 0; k < 8; k++) {
#pragma unroll
            for (int q = 0; q < 4; q++) g[q] = fmaf(y[k], we[k][q], g[q]);
        }
        float p0 = 0.f, p1 = 0.f;
#pragma unroll
        for (int q = 0; q < 4; q++) {
            float gq = leaky(g[q]);
            p0 = fmaf(gq, e2[q][0], p0);
            p1 = fmaf(gq, e2[q][1], p1);
        }

#pragma unroll
        for (int off = 16; off >= 1; off >>= 1) {
            o0 += __shfl_xor_sync(0xffffffffu, o0, off);
            o1 += __shfl_xor_sync(0xffffffffu, o1, off);
            p0 += __shfl_xor_sync(0xffffffffu, p0, off);
            p1 += __shfl_xor_sync(0xffffffffu, p1, off);
        }

        if (lane == 0 && valid) {
            g_node_f[row * 2 + 0] = tanhf(o0 + nb2x) * PI_F;
            g_node_f[row * 2 + 1] = tanhf(o1 + nb2y) * PI_F;
            g_eAB[row * 2 + 0] = (eidx >= 0) ? tanhf(p0 + eb2x) * PI_F : 0.f;
            g_eAB[row * 2 + 1] = (eidx >= 0) ? tanhf(p1 + eb2y) * PI_F : 0.f;
        }
    }
}

// ---------------- K2: 4 threads/row, 16-amp chi split over lanes -------------
// amp bits (local): q0=1, q4=2. Lane bits: q7 = sub&1 (xor 1), q8 = sub>>1 (xor 2).
// <X_q3> = 2*Re(conj(a0)a1) * <chi| M7 (x) M8 |chi>, M = U^dag Z U.

#define SHX(v, m) __shfl_xor_sync(0xffffffffu, (v), (m))

__global__ void __launch_bounds__(128, 1)
k2_pqc(int N, int mode, int G,
       const float* __restrict__ theta,
       const float* __restrict__ uW1, const float* __restrict__ ub1,
       const float* __restrict__ uW2, const float* __restrict__ ub2,
       const int* __restrict__ gn, const int* __restrict__ batch,
       const float* __restrict__ hW1, const float* __restrict__ hb1,
       const float* __restrict__ hW2, const float* __restrict__ hb2,
       float* __restrict__ out)
{
    __shared__ float sU[7][8];
    __shared__ float sM[6];
    __shared__ float4 sP1[128];
    __shared__ float2 sP2[128];
    __shared__ float sb2v[2];
    __shared__ int s_last;
    int tid = threadIdx.x;

    if (tid < 9) {
        int g = tid;
        float sx, cx, sy, cy, sz, cz;
        sincosf(0.5f * theta[3 * g + 0], &sx, &cx);
        sincosf(0.5f * theta[3 * g + 1], &sy, &cy);
        sincosf(0.5f * theta[3 * g + 2], &sz, &cz);
        float M00r =  cy*cx, M00i =  sy*sx;
        float M01r = -sy*cx, M01i = -cy*sx;
        float M10r =  sy*cx, M10i = -cy*sx;
        float M11r =  cy*cx, M11i = -sy*sx;
        float u[8];
        u[0] = cz*M00r + sz*M00i;  u[1] = cz*M00i - sz*M00r;
        u[2] = cz*M01r + sz*M01i;  u[3] = cz*M01i - sz*M01r;
        u[4] = cz*M10r - sz*M10i;  u[5] = cz*M10i + sz*M10r;
        u[6] = cz*M11r - sz*M11i;  u[7] = cz*M11i + sz*M11r;
        if (g < 7) {
#pragma unroll
            for (int k = 0; k < 8; k++) sU[g][k] = u[k];
        } else {
            int off = (g == 7) ? 0 : 3;
            sM[off + 0] = u[0]*u[0] + u[1]*u[1] - (u[4]*u[4] + u[5]*u[5]);
            sM[off + 1] = u[0]*u[2] + u[1]*u[3] - (u[4]*u[6] + u[5]*u[7]);
            sM[off + 2] = u[0]*u[3] - u[1]*u[2] - (u[4]*u[7] - u[5]*u[6]);
        }
    }
    for (int j = tid; j < 128; j += 128) {
        sP1[j] = make_float4(__ldg(uW1 + j), __ldg(uW1 + 128 + j),
                             __ldg(uW1 + 256 + j), __ldg(ub1 + j));
        sP2[j] = make_float2(__ldg(uW2 + 2*j + 0), __ldg(uW2 + 2*j + 1));
    }
    if (tid < 2) sb2v[tid] = ub2[tid];
    __syncthreads();

    int sub = tid & 3;
    int t7 = sub & 1, t8 = (sub >> 1) & 1;
    int row = (blockIdx.x * 128 + tid) >> 2;
    int i = min(row, N - 1);
    bool valid = row < N;

    int i0 = __ldg(gn + i * 4 + 0), i1 = __ldg(gn + i * 4 + 1);
    int i0c = max(i0, 0), i1c = max(i1, 0);
    float nf0u = g_node_f[i0c * 2 + 0];
    float nf1u = g_node_f[i0c * 2 + 1];
    float nA0 = (i0 >= 0) ? nf0u : 0.f;
    float nA1 = (i0 >= 0) ? nf1u : 0.f;
    float nB0 = (i1 >= 0) ? g_node_f[i1c * 2 + 0] : 0.f;
    float nB1 = (i1 >= 0) ? g_node_f[i1c * 2 + 1] : 0.f;
    float eA = g_eAB[i * 2 + 0], eB = g_eAB[i * 2 + 1];

    float cA, sA, cB, sB, c3a, s3a, c3b, s3b, c4a, s4a, c4b, s4b;
    __sincosf(0.5f * eA,  &sA,  &cA);
    __sincosf(0.5f * eB,  &sB,  &cB);
    __sincosf(0.5f * nA0, &s3a, &c3a);
    __sincosf(0.5f * nA1, &s3b, &c3b);
    __sincosf(0.5f * nB0, &s4a, &c4a);
    __sincosf(0.5f * nB1, &s4b, &c4b);

    // product init on (q0,q4); q7=q8=|0> -> only sub==0 nonzero
    float f0r0 = cA*cB,   f0i0 = -cA*sB,   f0r1 = sA*cB,   f0i1 = sA*sB;
    float f4r0 = c4a*c4b, f4i0 = -c4a*s4b, f4r1 = s4a*c4b, f4i1 = s4a*s4b;
    float mk = (sub == 0) ? 1.f : 0.f;

    float ar0 = mk*(f0r0*f4r0 - f0i0*f4i0), ai0 = mk*(f0r0*f4i0 + f0i0*f4r0);
    float ar1 = mk*(f0r1*f4r0 - f0i1*f4i0), ai1 = mk*(f0r1*f4i0 + f0i1*f4r0);
    float ar2 = mk*(f0r0*f4r1 - f0i0*f4i1), ai2 = mk*(f0r0*f4i1 + f0i0*f4r1);
    float ar3 = mk*(f0r1*f4r1 - f0i1*f4i1), ai3 = mk*(f0r1*f4i1 + f0i1*f4r1);

    // CRX(nB0): control q4 (amps 2,3), target q7 (xor 1). Symmetric.
#define CRX7(vr, vi) { float pr = SHX(vr,1), pi = SHX(vi,1); \
    float nr = c4a*vr + s4a*pi, ni = c4a*vi - s4a*pr; vr = nr; vi = ni; }
    CRX7(ar2, ai2) CRX7(ar3, ai3)

    // CRY(eA): control q0 (amps 1,3), target q7 (xor 1)
    {
        float ss = t7 ? sA : -sA;
#define CRY7(vr, vi) { float pr = SHX(vr,1), pi = SHX(vi,1); \
        vr = cA*vr + ss*pr; vi = cA*vi + ss*pi; }
        CRY7(ar1, ai1) CRY7(ar3, ai3)
#undef CRY7
    }

    // CRZ(nB1): control q4 (amps 2,3), target q8 -> diagonal phase by t8
    {
        float zs = t8 ? s4b : -s4b;
#define CRZ8(vr, vi) { float nr = c4b*vr - zs*vi, ni = c4b*vi + zs*vr; vr = nr; vi = ni; }
        CRZ8(ar2, ai2) CRZ8(ar3, ai3)
#undef CRZ8
    }

    // CRY(eB): control q0 (amps 1,3), target q8 (xor 2)
    {
        float ss = t8 ? sB : -sB;
#define CRY8(vr, vi) { float pr = SHX(vr,2), pi = SHX(vi,2); \
        vr = cB*vr + ss*pr; vi = cB*vi + ss*pi; }
        CRY8(ar1, ai1) CRY8(ar3, ai3)
#undef CRY8
    }

    float U0,U1,U2,U3,U4,U5,U6,U7;
#define LOADUg(g) { U0=sU[g][0]; U1=sU[g][1]; U2=sU[g][2]; U3=sU[g][3]; \
                    U4=sU[g][4]; U5=sU[g][5]; U6=sU[g][6]; U7=sU[g][7]; }
#define UPAIRL(lr,li,hr,hi) { float t0=lr,t1=li,t2=hr,t3=hi; \
    lr = U0*t0 - U1*t1 + U2*t2 - U3*t3; \
    li = U0*t1 + U1*t0 + U2*t3 + U3*t2; \
    hr = U4*t0 - U5*t1 + U6*t2 - U7*t3; \
    hi = U4*t1 + U5*t0 + U6*t3 + U7*t2; }
#define UCROSS(XB, tb) { \
    float Cmr = (tb)?U6:U0, Cmi = (tb)?U7:U1, Cpr = (tb)?U4:U2, Cpi = (tb)?U5:U3; \
    { float pr = SHX(ar0,XB), pi = SHX(ai0,XB); \
      float nr = Cmr*ar0 - Cmi*ai0 + Cpr*pr - Cpi*pi; \
      float ni = Cmr*ai0 + Cmi*ar0 + Cpr*pi + Cpi*pr; ar0 = nr; ai0 = ni; } \
    { float pr = SHX(ar1,XB), pi = SHX(ai1,XB); \
      float nr = Cmr*ar1 - Cmi*ai1 + Cpr*pr - Cpi*pi; \
      float ni = Cmr*ai1 + Cmi*ar1 + Cpr*pi + Cpi*pr; ar1 = nr; ai1 = ni; } \
    { float pr = SHX(ar2,XB), pi = SHX(ai2,XB); \
      float nr = Cmr*ar2 - Cmi*ai2 + Cpr*pr - Cpi*pi; \
      float ni = Cmr*ai2 + Cmi*ar2 + Cpr*pi + Cpi*pr; ar2 = nr; ai2 = ni; } \
    { float pr = SHX(ar3,XB), pi = SHX(ai3,XB); \
      float nr = Cmr*ar3 - Cmi*ai3 + Cpr*pr - Cpi*pi; \
      float ni = Cmr*ai3 + Cmi*ar3 + Cpr*pi + Cpi*pr; ar3 = nr; ai3 = ni; } }

    // Block 0: U0 on q0 (pairs 0-1, 2-3), U1 on q4 (pairs 0-2, 1-3), U2 on q7 (xor 1)
    LOADUg(0)
    UPAIRL(ar0, ai0, ar1, ai1)  UPAIRL(ar2, ai2, ar3, ai3)
    LOADUg(1)
    UPAIRL(ar0, ai0, ar2, ai2)  UPAIRL(ar1, ai1, ar3, ai3)
    LOADUg(2)
    UCROSS(1, t7)
    // CZ(0,4) CZ(4,7) CZ(7,0): flip amp3 always; amps 1,2 iff t7
    ar3 = -ar3; ai3 = -ai3;
    if (t7) { ar1 = -ar1; ai1 = -ai1; ar2 = -ar2; ai2 = -ai2; }

    // Block 1: U3 on q7 (xor 1), U4 on q4, U5 on q8 (xor 2)
    LOADUg(3)
    UCROSS(1, t7)
    LOADUg(4)
    UPAIRL(ar0, ai0, ar2, ai2)  UPAIRL(ar1, ai1, ar3, ai3)
    LOADUg(5)
    UCROSS(2, t8)
    // CZ(7,4) CZ(4,8) CZ(8,7): amps 0,1 flip iff t7&t8; amps 2,3 flip iff t7|t8
    if (t7 & t8) { ar0 = -ar0; ai0 = -ai0; ar1 = -ar1; ai1 = -ai1; }
    if (t7 | t8) { ar2 = -ar2; ai2 = -ai2; ar3 = -ar3; ai3 = -ai3; }

    // S = <chi| M7(q7) (x) M8(q8) |chi>
    float d7 = sM[0], k7r = sM[1], k7i = sM[2];
    float d8 = sM[3], k8r = sM[4], k8i = sM[5];
    float d8s = t8 ? -d8 : d8, k8is = t8 ? -k8i : k8i;
    float d7s = t7 ? -d7 : d7, k7is = t7 ? -k7i : k7i;
    float S = 0.f;
#define OBSM(vr, vi) { \
    float pr = SHX(vr,2), pi = SHX(vi,2); \
    float ur = d8s*vr + k8r*pr - k8is*pi; \
    float ui = d8s*vi + k8r*pi + k8is*pr; \
    float qr = SHX(ur,1), qi = SHX(ui,1); \
    float wr = d7s*ur + k7r*qr - k7is*qi; \
    float wi = d7s*ui + k7r*qi + k7is*qr; \
    S += vr*wr + vi*wi; }
    OBSM(ar0, ai0) OBSM(ar1, ai1) OBSM(ar2, ai2) OBSM(ar3, ai3)
    S += SHX(S, 1);
    S += SHX(S, 2);

    // q3 scalar
    LOADUg(6)
    {
        float p0r = c3a*c3b, p0i = -c3a*s3b, p1r = s3a*c3b, p1i = s3a*s3b;
        float a0r = U0*p0r - U1*p0i + U2*p1r - U3*p1i;
        float a0i = U0*p0i + U1*p0r + U2*p1i + U3*p1r;
        float a1r = U4*p0r - U5*p0i + U6*p1r - U7*p1i;
        float a1i = U4*p0i + U5*p0r + U6*p1i + U7*p1r;
        S *= 2.f * (a0r*a1r + a0i*a1i);
    }
    float ex = S;

    // upd MLP: 3 -> 128 (leaky) -> 2, hidden split j = 4u + sub
    float acc0 = 0.f, acc1 = 0.f;
#pragma unroll 8
    for (int u = 0; u < 32; u++) {
        int j = 4*u + sub;
        float4 wv = sP1[j];
        float h = fmaf(nf0u, wv.x, fmaf(nf1u, wv.y, fmaf(ex, wv.z, wv.w)));
        h = leaky(h);
        float2 v = sP2[j];
        acc0 = fmaf(h, v.x, acc0);
        acc1 = fmaf(h, v.y, acc1);
    }
    acc0 += SHX(acc0, 1); acc0 += SHX(acc0, 2);
    acc1 += SHX(acc1, 1); acc1 += SHX(acc1, 2);

    if (sub == 0 && valid) {
        acc0 += sb2v[0]; acc1 += sb2v[1];
        if (mode == 1) {
            int gi = batch[i];
            atomicAdd(&g_seg[gi * 2 + 0], g_node_f[i * 2 + 0]);
            atomicAdd(&g_seg[gi * 2 + 1], g_node_f[i * 2 + 1]);
            atomicAdd(&g_cnt[gi], 1.f);
            int gt = batch[i0c];
            atomicAdd(&g_seg[gt * 2 + 0], acc0);
            atomicAdd(&g_seg[gt * 2 + 1], acc1);
        } else {
            g_upd[i * 2 + 0] = acc0;
            g_upd[i * 2 + 1] = acc1;
        }
    }

    if (mode == 1) {
        __threadfence();
        __syncthreads();
        if (tid == 0) s_last = (atomicAdd(&g_ctr, 1) == (int)gridDim.x - 1) ? 1 : 0;
        __syncthreads();
        if (s_last) {
            for (int g = tid; g < G; g += 128) {
                float c = ldcg(&g_cnt[g]);
                float inv = (c > 0.f) ? (1.f / c) : 0.f;
                float e0 = ldcg(&g_seg[g * 2 + 0]) * inv;
                float e1 = ldcg(&g_seg[g * 2 + 1]) * inv;
                float h0 = leaky(e0 * hW1[0] + e1 * hW1[2] + hb1[0]);
                float h1 = leaky(e0 * hW1[1] + e1 * hW1[3] + hb1[1]);
                out[g * 2 + 0] = h0 * hW2[0] + h1 * hW2[2] + hb2[0];
                out[g * 2 + 1] = h0 * hW2[1] + h1 * hW2[3] + hb2[1];
            }
        }
    }
}

// ---------------- multi-hop helpers (H > 1 only) ----------------------------
__global__ void k2_scatter(int N, const int* __restrict__ gn)
{
    int i = blockIdx.x * blockDim.x + threadIdx.x;
    if (i >= N) return;
    int t = max(gn[i * 4], 0);
    atomicAdd(&g_node_f[t * 2 + 0], g_upd[i * 2 + 0]);
    atomicAdd(&g_node_f[t * 2 + 1], g_upd[i * 2 + 1]);
}

__global__ void k_seg(int N, const int* __restrict__ batch)
{
    int i = blockIdx.x * blockDim.x + threadIdx.x;
    if (i >= N) return;
    int g = batch[i];
    atomicAdd(&g_seg[g * 2 + 0], g_node_f[i * 2 + 0]);
    atomicAdd(&g_seg[g * 2 + 1], g_node_f[i * 2 + 1]);
    atomicAdd(&g_cnt[g], 1.f);
}

__global__ void k3_head(int G,
                        const float* __restrict__ hW1, const float* __restrict__ hb1,
                        const float* __restrict__ hW2, const float* __restrict__ hb2,
                        float* __restrict__ out)
{
    int g = blockIdx.x * blockDim.x + threadIdx.x;
    if (g >= G) return;
    float c = g_cnt[g];
    float inv = (c > 0.f) ? (1.f / c) : 0.f;
    float e0 = g_seg[g * 2 + 0] * inv;
    float e1 = g_seg[g * 2 + 1] * inv;
    float h0 = leaky(e0 * hW1[0] + e1 * hW1[2] + hb1[0]);
    float h1 = leaky(e0 * hW1[1] + e1 * hW1[3] + hb1[1]);
    out[g * 2 + 0] = h0 * hW2[0] + h1 * hW2[2] + hb2[0];
    out[g * 2 + 1] = h0 * hW2[1] + h1 * hW2[3] + hb2[1];
}

extern "C" void kernel_launch(void* const* d_in, const int* in_sizes, int n_in,
                              void* d_out, int out_size)
{
    const float* node_feat = (const float*)d_in[0];
    const float* edge_attr = (const float*)d_in[1];
    const float* nW1 = (const float*)d_in[2];
    const float* nb1 = (const float*)d_in[3];
    const float* nW2 = (const float*)d_in[4];
    const float* nb2 = (const float*)d_in[5];
    const float* eW1 = (const float*)d_in[6];
    const float* eb1 = (const float*)d_in[7];
    const float* eW2 = (const float*)d_in[8];
    const float* eb2 = (const float*)d_in[9];
    const float* theta = (const float*)d_in[10];
    const float* uW1 = (const float*)d_in[11];
    const float* ub1 = (const float*)d_in[12];
    const float* uW2 = (const float*)d_in[13];
    const float* ub2 = (const float*)d_in[14];
    const float* hW1 = (const float*)d_in[15];
    const float* hb1 = (const float*)d_in[16];
    const float* hW2 = (const float*)d_in[17];
    const float* hb2 = (const float*)d_in[18];
    const int* gn = (const int*)d_in[19];
    const int* ge = (const int*)d_in[20];
    const int* batch = (const int*)d_in[21];

    int N = in_sizes[0] / 16;
    int H = in_sizes[10] / 27;
    int G = out_size / 2;

    int k1blocks = (N + 15) / 16;
    k1_feat<<<k1blocks, 128>>>(node_feat, N, edge_attr, nW1, nb1, nW2, nb2,
                               eW1, eb1, eW2, eb2, ge);

    // k2: 4 threads/row, 128-thread blocks -> 32 rows per block
    int k2blocks = (N + 31) / 32;
    if (H == 1) {
        k2_pqc<<<k2blocks, 128>>>(N, 1, G, theta, uW1, ub1, uW2, ub2, gn, batch,
                                  hW1, hb1, hW2, hb2, (float*)d_out);
    } else {
        const int T = 128;
        int nbs = (N + T - 1) / T;
        for (int h = 0; h < H; h++) {
            k2_pqc<<<k2blocks, 128>>>(N, 0, G, theta + 27 * h,
                                      uW1 + 384 * h, ub1 + 128 * h,
                                      uW2 + 256 * h, ub2 + 2 * h, gn, batch,
                                      hW1, hb1, hW2, hb2, (float*)d_out);
            k2_scatter<<<nbs, T>>>(N, gn);
        }
        k_seg<<<nbs, T>>>(N, batch);
        k3_head<<<(G + 127) / 128, 128>>>(G, hW1, hb1, hW2, hb2, (float*)d_out);
    }
}